// round 2
// baseline (speedup 1.0000x reference)
#include <cuda_runtime.h>

#define UNITS   64
#define TT      512
#define BB      32
#define MOTOR   4
#define UNFOLDS 6
#define MROWS   (BB*TT)      // 16384

// ---------------- scratch (device globals: no allocation allowed) -----------
__device__ float g_buf0[MROWS * 500];
__device__ float g_buf1[MROWS * 500];
__device__ float g_h20 [MROWS * 20];
__device__ float g_o4  [MROWS * 4];

// ---------------- generic fused GEMM: C = act(A[M,K] @ W[K,N] + b) ----------
// BM=BN=128, BK=8, 256 threads, 8x8 per-thread tile.
template <int ACT>
__global__ __launch_bounds__(256)
void gemm_bias_act(const float* __restrict__ A, const float* __restrict__ W,
                   const float* __restrict__ bias, float* __restrict__ C,
                   int N, int K)
{
    __shared__ float As[8][128];
    __shared__ float Bs[8][132];   // pad to soften LDS conflicts

    const int tid = threadIdx.x;
    const int block_row = blockIdx.y * 128;
    const int block_col = blockIdx.x * 128;

    const int tx = tid & 15;       // 0..15
    const int ty = tid >> 4;       // 0..15

    // global-load mapping
    const int a_r = tid >> 1;             // 0..127
    const int a_c = (tid & 1) * 4;        // 0 or 4
    const int b_r = tid >> 5;             // 0..7  (k)
    const int b_c = (tid & 31) * 4;       // 0..124

    float acc[8][8];
#pragma unroll
    for (int i = 0; i < 8; i++)
#pragma unroll
        for (int j = 0; j < 8; j++) acc[i][j] = 0.f;

    for (int k0 = 0; k0 < K; k0 += 8) {
#pragma unroll
        for (int u = 0; u < 4; u++) {
            int k = k0 + a_c + u;
            As[a_c + u][a_r] = (k < K) ? A[(size_t)(block_row + a_r) * K + k] : 0.f;
        }
        {
            int k = k0 + b_r;
#pragma unroll
            for (int u = 0; u < 4; u++) {
                int col = block_col + b_c + u;
                Bs[b_r][b_c + u] = (k < K && col < N) ? W[(size_t)k * N + col] : 0.f;
            }
        }
        __syncthreads();

#pragma unroll
        for (int kk = 0; kk < 8; kk++) {
            float ar[8], br[8];
#pragma unroll
            for (int i = 0; i < 8; i++) ar[i] = As[kk][ty * 8 + i];
#pragma unroll
            for (int j = 0; j < 8; j++) br[j] = Bs[kk][tx * 8 + j];
#pragma unroll
            for (int i = 0; i < 8; i++)
#pragma unroll
                for (int j = 0; j < 8; j++)
                    acc[i][j] += ar[i] * br[j];
        }
        __syncthreads();
    }

#pragma unroll
    for (int i = 0; i < 8; i++) {
        int row = block_row + ty * 8 + i;
#pragma unroll
        for (int j = 0; j < 8; j++) {
            int col = block_col + tx * 8 + j;
            if (col < N) {
                float v = acc[i][j] + bias[col];
                if (ACT) v = tanhf(v);
                C[(size_t)row * N + col] = v;
            }
        }
    }
}

// ---------------- LTC scan: one CTA per batch element ------------------------
// 512 threads: thread = j*8 + isub; column j in [0,64), isub owns 8 presynaptic
// rows i = isub*8+m. All synapse constants register-resident. v[64] ping-pongs
// through shared memory, one barrier per ODE unfold. h[T,20] staged in SMEM.
__global__ __launch_bounds__(512)
void ltc_scan(const float* __restrict__ h20, float* __restrict__ o4,
              const float* __restrict__ gleak, const float* __restrict__ vleak,
              const float* __restrict__ cm,    const float* __restrict__ w,
              const float* __restrict__ mu,    const float* __restrict__ sigma,
              const float* __restrict__ erev,  const float* __restrict__ sw,
              const float* __restrict__ smu,   const float* __restrict__ ssigma,
              const float* __restrict__ serev, const float* __restrict__ in_w,
              const float* __restrict__ in_b,  const float* __restrict__ out_w,
              const float* __restrict__ out_b)
{
    __shared__ float sh_h[TT * 20];
    __shared__ float sv[2][UNITS];

    const int b    = blockIdx.x;
    const int tid  = threadIdx.x;
    const int j    = tid >> 3;
    const int isub = tid & 7;

    // ---- register-resident recurrent synapse constants (8 per thread) ----
    float sg[8], ms[8], we[8], wr[8];
#pragma unroll
    for (int m = 0; m < 8; m++) {
        int i   = isub * 8 + m;
        int idx = i * UNITS + j;
        float s_ = sigma[idx];
        sg[m] = s_;
        ms[m] = mu[idx] * s_;
        float wv = w[idx];
        wr[m] = wv;
        we[m] = wv * erev[idx];
    }

    // ---- sensory synapse constants: k = isub + 8m, m < kcnt ----
    const int kcnt = (isub < 4) ? 3 : 2;
    float ssg[3], sms[3], swe[3], swr[3], siw[3], sib[3];
#pragma unroll
    for (int m = 0; m < 3; m++) {
        if (m < kcnt) {
            int k   = isub + 8 * m;
            int idx = k * UNITS + j;
            float s_ = ssigma[idx];
            ssg[m] = s_;
            sms[m] = smu[idx] * s_;
            float wv = sw[idx];
            swr[m] = wv;
            swe[m] = wv * serev[idx];
            siw[m] = in_w[k];
            sib[m] = in_b[k];
        } else {
            ssg[m] = sms[m] = swe[m] = swr[m] = siw[m] = sib[m] = 0.f;
        }
    }

    const float cmt  = cm[j] * (float)UNFOLDS;   // cm / (1.0/6)
    const float glv  = gleak[j] * vleak[j];
    const float den0 = cmt + gleak[j];
    float ow = 0.f, ob = 0.f;
    if (j < MOTOR) { ow = out_w[j]; ob = out_b[j]; }

    // ---- stage full h sequence for this batch into SMEM ----
    for (int idx = tid; idx < TT * 20; idx += 512)
        sh_h[idx] = h20[(size_t)b * (TT * 20) + idx];
    if (tid < UNITS) sv[0][tid] = 0.f;
    __syncthreads();

    int   p  = 0;
    float vj = 0.f;

    for (int t = 0; t < TT; t++) {
        // ---- sensory contribution (once per step): per-lane partials,
        //      reduced over the 8-lane group to the full k=0..19 sum ----
        float wns = 0.f, wds = 0.f;
#pragma unroll
        for (int m = 0; m < 3; m++) {
            if (m < kcnt) {
                float uk = sh_h[t * 20 + (isub + 8 * m)];
                uk = uk * siw[m] + sib[m];
                float e = __expf(sms[m] - uk * ssg[m]);   // exp(-(ui-smu)*ssig)
                float s = __fdividef(1.f, 1.f + e);
                wns += swe[m] * s;
                wds += swr[m] * s;
            }
        }
#pragma unroll
        for (int off = 1; off < 8; off <<= 1) {
            wns += __shfl_xor_sync(0xffffffffu, wns, off);
            wds += __shfl_xor_sync(0xffffffffu, wds, off);
        }
        // wns/wds now hold the FULL sensory sums, identical on all 8 lanes.

        // ---- 6 semi-implicit ODE unfolds ----
#pragma unroll
        for (int uf = 0; uf < UNFOLDS; uf++) {
            float an = 0.f, ad = 0.f;          // per-lane recurrent partials ONLY
#pragma unroll
            for (int m = 0; m < 8; m++) {
                float vi = sv[p][isub * 8 + m];
                float e  = __expf(ms[m] - vi * sg[m]);    // exp(-(v-mu)*sigma)
                float s  = __fdividef(1.f, 1.f + e);
                an += we[m] * s;
                ad += wr[m] * s;
            }
#pragma unroll
            for (int off = 1; off < 8; off <<= 1) {
                an += __shfl_xor_sync(0xffffffffu, an, off);
                ad += __shfl_xor_sync(0xffffffffu, ad, off);
            }
            an += wns;                          // add reduced sensory sums ONCE
            ad += wds;
            vj = (cmt * vj + glv + an) * __fdividef(1.f, den0 + ad + 1e-8f);
            if (isub == 0) sv[p ^ 1][j] = vj;
            __syncthreads();
            p ^= 1;
        }

        // ---- motor readout ----
        if (j < MOTOR && isub == 0)
            o4[((size_t)b * TT + t) * MOTOR + j] = vj * ow + ob;
    }
}

// ---------------- launcher ---------------------------------------------------
extern "C" void kernel_launch(void* const* d_in, const int* in_sizes, int n_in,
                              void* d_out, int out_size)
{
    const float* x     = (const float*)d_in[0];
    const float* ew0   = (const float*)d_in[1];
    const float* eb0   = (const float*)d_in[2];
    const float* ew1   = (const float*)d_in[3];
    const float* eb1   = (const float*)d_in[4];
    const float* ew2   = (const float*)d_in[5];
    const float* eb2   = (const float*)d_in[6];
    const float* dw0   = (const float*)d_in[7];
    const float* db0   = (const float*)d_in[8];
    const float* dw1   = (const float*)d_in[9];
    const float* db1   = (const float*)d_in[10];
    const float* dw2   = (const float*)d_in[11];
    const float* db2   = (const float*)d_in[12];
    const float* gleak = (const float*)d_in[13];
    const float* vleak = (const float*)d_in[14];
    const float* cm    = (const float*)d_in[15];
    const float* w     = (const float*)d_in[16];
    const float* mu    = (const float*)d_in[17];
    const float* sigma = (const float*)d_in[18];
    const float* erev  = (const float*)d_in[19];
    const float* sw    = (const float*)d_in[20];
    const float* smu   = (const float*)d_in[21];
    const float* ssig  = (const float*)d_in[22];
    const float* serev = (const float*)d_in[23];
    const float* in_w  = (const float*)d_in[24];
    const float* in_b  = (const float*)d_in[25];
    const float* out_w = (const float*)d_in[26];
    const float* out_b = (const float*)d_in[27];
    float* out = (float*)d_out;

    float *buf0, *buf1, *h20, *o4;
    cudaGetSymbolAddress((void**)&buf0, g_buf0);
    cudaGetSymbolAddress((void**)&buf1, g_buf1);
    cudaGetSymbolAddress((void**)&h20,  g_h20);
    cudaGetSymbolAddress((void**)&o4,   g_o4);

    dim3 blk(256);
    dim3 grid500(4, MROWS / 128);   // N=500 -> 4 col blocks
    dim3 grid1(1, MROWS / 128);     // N<=128

    // encoder: 39 -> 500 -> 500 -> 20
    gemm_bias_act<1><<<grid500, blk>>>(x,    ew0, eb0, buf0, 500, 39);
    gemm_bias_act<1><<<grid500, blk>>>(buf0, ew1, eb1, buf1, 500, 500);
    gemm_bias_act<0><<<grid1,   blk>>>(buf1, ew2, eb2, h20,  20,  500);

    // LTC scan over T
    ltc_scan<<<BB, 512>>>(h20, o4, gleak, vleak, cm, w, mu, sigma, erev,
                          sw, smu, ssig, serev, in_w, in_b, out_w, out_b);

    // decoder: 4 -> 500 -> 500 -> 30
    gemm_bias_act<1><<<grid500, blk>>>(o4,   dw0, db0, buf0, 500, 4);
    gemm_bias_act<1><<<grid500, blk>>>(buf0, dw1, db1, buf1, 500, 500);
    gemm_bias_act<0><<<grid1,   blk>>>(buf1, dw2, db2, out,  30,  500);
}

// round 3
// speedup vs baseline: 1.2383x; 1.2383x over previous
#include <cuda_runtime.h>

#define UNITS   64
#define TT      512
#define BB      32
#define MOTOR   4
#define UNFOLDS 6
#define MROWS   (BB*TT)      // 16384

// ---------------- scratch (device globals: no allocation allowed) -----------
__device__ float g_buf0[MROWS * 500];
__device__ float g_buf1[MROWS * 500];
__device__ float g_h20 [MROWS * 20];
__device__ float g_o4  [MROWS * 4];

__device__ __forceinline__ float fast_tanh(float x) {
    float r;
    asm("tanh.approx.f32 %0, %1;" : "=f"(r) : "f"(x));
    return r;
}
__device__ __forceinline__ float fast_rcp(float x) {
    float r;
    asm("rcp.approx.f32 %0, %1;" : "=f"(r) : "f"(x));
    return r;
}

// ---------------- fused GEMM: C = act(A[M,K] @ W[K,N] + b) -------------------
// BM=BN=128, BK=8, 256 threads, 8x8 per-thread tile, double-buffered SMEM
// with register prefetch (1 barrier per K-iteration).
template <int ACT>
__global__ __launch_bounds__(256, 2)
void gemm_bias_act(const float* __restrict__ A, const float* __restrict__ W,
                   const float* __restrict__ bias, float* __restrict__ C,
                   int N, int K)
{
    __shared__ float As[2][8][128];
    __shared__ float Bs[2][8][132];   // pad to soften LDS conflicts

    const int tid = threadIdx.x;
    const int block_row = blockIdx.y * 128;
    const int block_col = blockIdx.x * 128;

    const int tx = tid & 15;       // 0..15
    const int ty = tid >> 4;       // 0..15

    // global-load mapping
    const int a_r = tid >> 1;             // 0..127
    const int a_c = (tid & 1) * 4;        // 0 or 4
    const int b_r = tid >> 5;             // 0..7  (k)
    const int b_c = (tid & 31) * 4;       // 0..124

    const float* Arow = A + (size_t)(block_row + a_r) * K;

    float acc[8][8];
#pragma unroll
    for (int i = 0; i < 8; i++)
#pragma unroll
        for (int j = 0; j < 8; j++) acc[i][j] = 0.f;

    const int niter = (K + 7) / 8;
    float ra[4], rb[4];

    // ---- prefetch tile 0 into registers, stage to smem buf 0 ----
    {
#pragma unroll
        for (int u = 0; u < 4; u++) {
            int k = a_c + u;
            ra[u] = (k < K) ? Arow[k] : 0.f;
        }
        int kb = b_r;
#pragma unroll
        for (int u = 0; u < 4; u++) {
            int col = block_col + b_c + u;
            rb[u] = (kb < K && col < N) ? W[(size_t)kb * N + col] : 0.f;
        }
#pragma unroll
        for (int u = 0; u < 4; u++) As[0][a_c + u][a_r] = ra[u];
#pragma unroll
        for (int u = 0; u < 4; u++) Bs[0][b_r][b_c + u] = rb[u];
    }
    __syncthreads();

    for (int it = 0; it < niter; it++) {
        const int p = it & 1;

        // ---- prefetch next tile (overlaps with FFMA below) ----
        if (it + 1 < niter) {
            int k0 = (it + 1) * 8;
#pragma unroll
            for (int u = 0; u < 4; u++) {
                int k = k0 + a_c + u;
                ra[u] = (k < K) ? Arow[k] : 0.f;
            }
            int kb = k0 + b_r;
#pragma unroll
            for (int u = 0; u < 4; u++) {
                int col = block_col + b_c + u;
                rb[u] = (kb < K && col < N) ? W[(size_t)kb * N + col] : 0.f;
            }
        }

        // ---- compute on buffer p ----
#pragma unroll
        for (int kk = 0; kk < 8; kk++) {
            float ar[8], br[8];
#pragma unroll
            for (int i = 0; i < 8; i++) ar[i] = As[p][kk][ty * 8 + i];
#pragma unroll
            for (int j = 0; j < 8; j++) br[j] = Bs[p][kk][tx * 8 + j];
#pragma unroll
            for (int i = 0; i < 8; i++)
#pragma unroll
                for (int j = 0; j < 8; j++)
                    acc[i][j] += ar[i] * br[j];
        }

        // ---- stage next tile into the other buffer ----
        if (it + 1 < niter) {
#pragma unroll
            for (int u = 0; u < 4; u++) As[p ^ 1][a_c + u][a_r] = ra[u];
#pragma unroll
            for (int u = 0; u < 4; u++) Bs[p ^ 1][b_r][b_c + u] = rb[u];
        }
        __syncthreads();
    }

#pragma unroll
    for (int i = 0; i < 8; i++) {
        int row = block_row + ty * 8 + i;
#pragma unroll
        for (int j = 0; j < 8; j++) {
            int col = block_col + tx * 8 + j;
            if (col < N) {
                float v = acc[i][j] + bias[col];
                if (ACT) v = tanhf(v);
                C[(size_t)row * N + col] = v;
            }
        }
    }
}

// ---------------- LTC scan: one CTA per batch element ------------------------
// 512 threads: thread = j*8 + isub; column j in [0,64), isub owns 8 presynaptic
// rows i = isub*8+m. Sigmoid via single-MUFU tanh.approx:
//   sigmoid(x) = 0.5 + 0.5*tanh(0.5*x)
// The 0.5*w / 0.5*w*erev constant halves are folded into register constants and
// the "+0.5" part into per-column init-time reduced constants.
__global__ __launch_bounds__(512)
void ltc_scan(const float* __restrict__ h20, float* __restrict__ o4,
              const float* __restrict__ gleak, const float* __restrict__ vleak,
              const float* __restrict__ cm,    const float* __restrict__ w,
              const float* __restrict__ mu,    const float* __restrict__ sigma,
              const float* __restrict__ erev,  const float* __restrict__ sw,
              const float* __restrict__ smu,   const float* __restrict__ ssigma,
              const float* __restrict__ serev, const float* __restrict__ in_w,
              const float* __restrict__ in_b,  const float* __restrict__ out_w,
              const float* __restrict__ out_b)
{
    __shared__ float sh_h[TT * 20];
    __shared__ float sv[2][UNITS];

    const int b    = blockIdx.x;
    const int tid  = threadIdx.x;
    const int j    = tid >> 3;
    const int isub = tid & 7;

    // ---- recurrent synapse constants (8 per thread), tanh-folded ----
    // x = (v - mu)*sigma; 0.5*x = v*ha[m] - hb[m]
    float ha[8], hb[8], we2[8], wr2[8];
    float cnum = 0.f, cden = 0.f;      // 0.5 * sum(w*erev), 0.5 * sum(w) partials
#pragma unroll
    for (int m = 0; m < 8; m++) {
        int i   = isub * 8 + m;
        int idx = i * UNITS + j;
        float s_ = sigma[idx];
        ha[m] = 0.5f * s_;
        hb[m] = 0.5f * mu[idx] * s_;
        float wv = 0.5f * w[idx];
        wr2[m] = wv;
        we2[m] = wv * erev[idx];
        cnum += we2[m];
        cden += wr2[m];
    }

    // ---- sensory synapse constants: k = isub + 8m, m < kcnt ----
    // ui = u*in_w + in_b; 0.5*(ui - smu)*ssigma = u*sA[m] + sB[m]
    const int kcnt = (isub < 4) ? 3 : 2;
    float sA[3], sB[3], swe2[3], swr2[3];
#pragma unroll
    for (int m = 0; m < 3; m++) {
        if (m < kcnt) {
            int k   = isub + 8 * m;
            int idx = k * UNITS + j;
            float s_ = ssigma[idx];
            sA[m] = 0.5f * in_w[k] * s_;
            sB[m] = 0.5f * (in_b[k] - smu[idx]) * s_;
            float wv = 0.5f * sw[idx];
            swr2[m] = wv;
            swe2[m] = wv * serev[idx];
            cnum += swe2[m];
            cden += swr2[m];
        } else {
            sA[m] = sB[m] = swe2[m] = swr2[m] = 0.f;
        }
    }

    // reduce constant halves over the 8-lane group (full sums per column j)
#pragma unroll
    for (int off = 1; off < 8; off <<= 1) {
        cnum += __shfl_xor_sync(0xffffffffu, cnum, off);
        cden += __shfl_xor_sync(0xffffffffu, cden, off);
    }

    const float cmt    = cm[j] * (float)UNFOLDS;        // cm / (1/6)
    const float addnum = gleak[j] * vleak[j] + cnum;    // gleak*vleak + 0.5*sum(we)
    const float denbas = cmt + gleak[j] + cden + 1e-8f; // + 0.5*sum(w)
    float ow = 0.f, ob = 0.f;
    if (j < MOTOR) { ow = out_w[j]; ob = out_b[j]; }

    // ---- stage full h sequence for this batch into SMEM ----
    for (int idx = tid; idx < TT * 20; idx += 512)
        sh_h[idx] = h20[(size_t)b * (TT * 20) + idx];
    if (tid < UNITS) sv[0][tid] = 0.f;
    __syncthreads();

    int   p  = 0;
    float vj = 0.f;

    for (int t = 0; t < TT; t++) {
        // ---- sensory tanh-part (once per step), reduced over 8-lane group ----
        float wns = 0.f, wds = 0.f;
#pragma unroll
        for (int m = 0; m < 3; m++) {
            if (m < kcnt) {
                float uk = sh_h[t * 20 + (isub + 8 * m)];
                float tt = fast_tanh(fmaf(uk, sA[m], sB[m]));
                wns = fmaf(swe2[m], tt, wns);
                wds = fmaf(swr2[m], tt, wds);
            }
        }
#pragma unroll
        for (int off = 1; off < 8; off <<= 1) {
            wns += __shfl_xor_sync(0xffffffffu, wns, off);
            wds += __shfl_xor_sync(0xffffffffu, wds, off);
        }

        // ---- 6 semi-implicit ODE unfolds ----
#pragma unroll
        for (int uf = 0; uf < UNFOLDS; uf++) {
            float an = 0.f, ad = 0.f;
#pragma unroll
            for (int m = 0; m < 8; m++) {
                float vi = sv[p][isub * 8 + m];
                float tt = fast_tanh(fmaf(vi, ha[m], -hb[m]));
                an = fmaf(we2[m], tt, an);
                ad = fmaf(wr2[m], tt, ad);
            }
#pragma unroll
            for (int off = 1; off < 8; off <<= 1) {
                an += __shfl_xor_sync(0xffffffffu, an, off);
                ad += __shfl_xor_sync(0xffffffffu, ad, off);
            }
            float num = fmaf(cmt, vj, addnum) + an + wns;
            float den = denbas + ad + wds;
            vj = num * fast_rcp(den);
            if (isub == 0) sv[p ^ 1][j] = vj;
            __syncthreads();
            p ^= 1;
        }

        // ---- motor readout ----
        if (j < MOTOR && isub == 0)
            o4[((size_t)b * TT + t) * MOTOR + j] = fmaf(vj, ow, ob);
    }
}

// ---------------- launcher ---------------------------------------------------
extern "C" void kernel_launch(void* const* d_in, const int* in_sizes, int n_in,
                              void* d_out, int out_size)
{
    const float* x     = (const float*)d_in[0];
    const float* ew0   = (const float*)d_in[1];
    const float* eb0   = (const float*)d_in[2];
    const float* ew1   = (const float*)d_in[3];
    const float* eb1   = (const float*)d_in[4];
    const float* ew2   = (const float*)d_in[5];
    const float* eb2   = (const float*)d_in[6];
    const float* dw0   = (const float*)d_in[7];
    const float* db0   = (const float*)d_in[8];
    const float* dw1   = (const float*)d_in[9];
    const float* db1   = (const float*)d_in[10];
    const float* dw2   = (const float*)d_in[11];
    const float* db2   = (const float*)d_in[12];
    const float* gleak = (const float*)d_in[13];
    const float* vleak = (const float*)d_in[14];
    const float* cm    = (const float*)d_in[15];
    const float* w     = (const float*)d_in[16];
    const float* mu    = (const float*)d_in[17];
    const float* sigma = (const float*)d_in[18];
    const float* erev  = (const float*)d_in[19];
    const float* sw    = (const float*)d_in[20];
    const float* smu   = (const float*)d_in[21];
    const float* ssig  = (const float*)d_in[22];
    const float* serev = (const float*)d_in[23];
    const float* in_w  = (const float*)d_in[24];
    const float* in_b  = (const float*)d_in[25];
    const float* out_w = (const float*)d_in[26];
    const float* out_b = (const float*)d_in[27];
    float* out = (float*)d_out;

    float *buf0, *buf1, *h20, *o4;
    cudaGetSymbolAddress((void**)&buf0, g_buf0);
    cudaGetSymbolAddress((void**)&buf1, g_buf1);
    cudaGetSymbolAddress((void**)&h20,  g_h20);
    cudaGetSymbolAddress((void**)&o4,   g_o4);

    dim3 blk(256);
    dim3 grid500(4, MROWS / 128);   // N=500 -> 4 col blocks
    dim3 grid1(1, MROWS / 128);     // N<=128

    // encoder: 39 -> 500 -> 500 -> 20
    gemm_bias_act<1><<<grid500, blk>>>(x,    ew0, eb0, buf0, 500, 39);
    gemm_bias_act<1><<<grid500, blk>>>(buf0, ew1, eb1, buf1, 500, 500);
    gemm_bias_act<0><<<grid1,   blk>>>(buf1, ew2, eb2, h20,  20,  500);

    // LTC scan over T
    ltc_scan<<<BB, 512>>>(h20, o4, gleak, vleak, cm, w, mu, sigma, erev,
                          sw, smu, ssig, serev, in_w, in_b, out_w, out_b);

    // decoder: 4 -> 500 -> 500 -> 30
    gemm_bias_act<1><<<grid500, blk>>>(o4,   dw0, db0, buf0, 500, 4);
    gemm_bias_act<1><<<grid500, blk>>>(buf0, dw1, db1, buf1, 500, 500);
    gemm_bias_act<0><<<grid1,   blk>>>(buf1, dw2, db2, out,  30,  500);
}